// round 9
// baseline (speedup 1.0000x reference)
#include <cuda_runtime.h>
#include <math.h>

#define NB   16
#define NI   127
#define NN   16129      // 127*127
#define IMG  65536      // 256*256
#define TS   32
#define HL2  11
#define LT2  54         // TS + 2*HL2
#define LTN  2916       // LT2*LT2

typedef unsigned long long u64;

// ---------------- scratch (static device globals) ----------------------------
static __device__ float  g_x[NB * NN];
static __device__ float  g_r[NB * NN];
static __device__ float2 g_FA[NB * IMG];
static __device__ float2 g_FB[NB * IMG];   // also reused as float (real) buffer
static __device__ float2 g_part[1024];

// ---------------- packed f32x2 helpers ---------------------------------------
__device__ __forceinline__ u64 pk2(float lo, float hi) {
    u64 r; asm("mov.b64 %0, {%1, %2};" : "=l"(r) : "f"(lo), "f"(hi)); return r;
}
__device__ __forceinline__ float2 upk(u64 v) {
    float2 r; asm("mov.b64 {%0, %1}, %2;" : "=f"(r.x), "=f"(r.y) : "l"(v)); return r;
}
__device__ __forceinline__ void cfma(u64& acc, u64 a, u64 b) {
    asm("fma.rn.f32x2 %0, %1, %2, %0;" : "+l"(acc) : "l"(a), "l"(b));
}

// ---------------- misc helpers ------------------------------------------------
__device__ __forceinline__ int get_K(const int* ep) {
    int ei = *ep;
    int e;
    if (ei > 0 && ei <= 1000000) {
        e = ei;
    } else {
        float ff = __int_as_float(ei);
        e = (ff >= 1.0f && ff <= 1000000.0f) ? (int)ff : 120;
    }
    int K = (e - 1) / 40 + 1;
    if (K > 10) K = 10;
    if (K < 1)  K = 1;
    return K;
}

// base-4 digit reversal of 8-bit index
__device__ __forceinline__ int dr4(int p) {
    return ((p & 3) << 6) | (((p >> 2) & 3) << 4) | (((p >> 4) & 3) << 2) | ((p >> 6) & 3);
}

__device__ __forceinline__ float2 cmulf(float2 a, float2 b) {
    return make_float2(a.x * b.x - a.y * b.y, a.x * b.y + a.y * b.x);
}

__device__ __forceinline__ void build_tw(float2* tw, int tid, float sign) {
    if (tid < 192) {
        float s, c;
        __sincosf(sign * 6.283185307179586f * (float)tid * (1.0f / 256.0f), &s, &c);
        tw[tid] = make_float2(c, s);
    }
}

// Radix-4 256-pt DIT FFT, input base-4 digit-reversed, output natural.
// 64 butterflies/stage, t in 0..63; 4 stages. SGN=+1 inverse / -1 forward.
template <int STRIDE, int SGN>
__device__ __forceinline__ void fft256_r4(float2* s, const float2* tw, int t) {
#pragma unroll
    for (int st = 0; st < 4; ++st) {
        int L    = 1 << (2 * st);
        int k    = t & (L - 1);
        int g    = t >> (2 * st);
        int i0   = g * 4 * L + k;
        int step = 64 >> (2 * st);
        float2 a = s[i0 * STRIDE];
        float2 b = s[(i0 + L) * STRIDE];
        float2 c = s[(i0 + 2 * L) * STRIDE];
        float2 d = s[(i0 + 3 * L) * STRIDE];
        b = cmulf(b, tw[k * step]);
        c = cmulf(c, tw[2 * k * step]);
        d = cmulf(d, tw[3 * k * step]);
        float2 t0 = make_float2(a.x + c.x, a.y + c.y);
        float2 t1 = make_float2(a.x - c.x, a.y - c.y);
        float2 t2 = make_float2(b.x + d.x, b.y + d.y);
        float2 t3 = make_float2(b.x - d.x, b.y - d.y);
        float2 rot = make_float2(-(float)SGN * t3.y, (float)SGN * t3.x);
        s[i0 * STRIDE]           = make_float2(t0.x + t2.x, t0.y + t2.y);
        s[(i0 + L) * STRIDE]     = make_float2(t1.x + rot.x, t1.y + rot.y);
        s[(i0 + 2 * L) * STRIDE] = make_float2(t0.x - t2.x, t0.y - t2.y);
        s[(i0 + 3 * L) * STRIDE] = make_float2(t1.x - rot.x, t1.y - rot.y);
        __syncthreads();
    }
}

// ---------------- kernels ----------------------------------------------------
// Sweep-chunked Jacobi with rolling 3-row register window.
// Thread = column tx (0..53 of 64) x 7-row strip; 3 LDS per stencil point.
__global__ void __launch_bounds__(512)
jacobi_tile(const float* __restrict__ f, const float* __restrict__ kA,
            const int* __restrict__ ep, int iter, int final_, int zero) {
    if (iter >= get_K(ep)) return;
    __shared__ float xs0[LTN], xs1[LTN], fs[LTN];
    int b  = blockIdx.z;
    int ox = blockIdx.x * TS - HL2;
    int oy = blockIdx.y * TS - HL2;
    int tid = threadIdx.x;
    const float* ka = kA + b * 9;
    float k0 = ka[0], k1 = ka[1], k2 = ka[2], k3 = ka[3], k4 = ka[4];
    float k5 = ka[5], k6 = ka[6], k7 = ka[7], k8 = ka[8];
    float tau = 0.5f / k4;

    // ---- load tile (linear, coalesced) ----
#pragma unroll
    for (int k = 0; k < 6; ++k) {
        int p = tid + k * 512;
        if (p < LTN) {
            int iy = p / LT2, ix = p - iy * LT2;
            int gy = oy + iy, gx = ox + ix;
            bool dom = ((unsigned)gy < 127u) && ((unsigned)gx < 127u);
            xs0[p] = (dom && !zero) ? g_x[b * NN + gy * 127 + gx] : 0.0f;
            fs[p]  = dom ? f[b * NN + gy * 127 + gx] : 0.0f;
        }
    }
    __syncthreads();

    int tx = tid & 63;                    // column (valid < 54)
    int ts = tid >> 6;                    // strip 0..7
    int y0 = ts * 7;
    int y1 = min(54, y0 + 7);
    bool colv = (tx < 54);
    int gx = ox + tx;
    bool domx = colv && ((unsigned)gx < 127u);

    // preload f for the strip
    float freg[7];
    if (colv) {
#pragma unroll
        for (int i = 0; i < 7; ++i) {
            int y = y0 + i;
            freg[i] = (y < y1) ? fs[y * LT2 + tx] : 0.0f;
        }
    }

    float* cur = xs0;
    float* nxt = xs1;
#pragma unroll
    for (int s = 0; s < 10; ++s) {
        int a = s + 1;
        if (colv) {
            float am, a0, ap, bm, b0, bp;
            if (y0 > 0) {
                int r_ = (y0 - 1) * LT2;
                am = (tx > 0)  ? cur[r_ + tx - 1] : 0.0f;
                a0 = cur[r_ + tx];
                ap = (tx < 53) ? cur[r_ + tx + 1] : 0.0f;
            } else { am = a0 = ap = 0.0f; }
            {
                int r_ = y0 * LT2;
                bm = (tx > 0)  ? cur[r_ + tx - 1] : 0.0f;
                b0 = cur[r_ + tx];
                bp = (tx < 53) ? cur[r_ + tx + 1] : 0.0f;
            }
#pragma unroll
            for (int i = 0; i < 7; ++i) {
                int y = y0 + i;
                if (y >= y1) break;
                float cm, c0, cp;
                if (y + 1 < 54) {
                    int r_ = (y + 1) * LT2;
                    cm = (tx > 0)  ? cur[r_ + tx - 1] : 0.0f;
                    c0 = cur[r_ + tx];
                    cp = (tx < 53) ? cur[r_ + tx + 1] : 0.0f;
                } else { cm = c0 = cp = 0.0f; }
                float nv = b0;
                int gy = oy + y;
                if (domx && ((unsigned)gy < 127u) &&
                    y >= a && y < 54 - a && tx >= a && tx < 54 - a) {
                    float ax = k0 * am + k1 * a0 + k2 * ap
                             + k3 * bm + k4 * b0 + k5 * bp
                             + k6 * cm + k7 * c0 + k8 * cp;
                    nv = b0 + tau * (freg[i] - ax);
                }
                nxt[y * LT2 + tx] = nv;
                am = bm; a0 = b0; ap = bp;
                bm = cm; b0 = c0; bp = cp;
            }
        }
        __syncthreads();
        float* tsw = cur; cur = nxt; nxt = tsw;
    }

    // ---- epilogue: write x (and r) on 32x32 interior ----
#pragma unroll
    for (int k = 0; k < 2; ++k) {
        int p2 = tid + k * 512;
        int py = p2 >> 5, px = p2 & 31;
        int iy = HL2 + py, ix = HL2 + px;
        int gy = oy + iy, gxx = ox + ix;
        if (((unsigned)gy < 127u) && ((unsigned)gxx < 127u)) {
            int i = iy * LT2 + ix;
            g_x[b * NN + gy * 127 + gxx] = cur[i];
            if (final_) {
                float ax = k0 * cur[i - LT2 - 1] + k1 * cur[i - LT2] + k2 * cur[i - LT2 + 1]
                         + k3 * cur[i - 1]       + k4 * cur[i]       + k5 * cur[i + 1]
                         + k6 * cur[i + LT2 - 1] + k7 * cur[i + LT2] + k8 * cur[i + LT2 + 1];
                g_r[b * NN + gy * 127 + gxx] = fs[i] - ax;
            }
        }
    }
}

// ifft2 pass 1 (odd symmetry): FFT rows 1..127; store only k=0..127.
__global__ void __launch_bounds__(512)
fft_row_expand(const int* __restrict__ ep, int iter) {
    if (iter >= get_K(ep)) return;
    __shared__ float2 s[8][256];
    __shared__ float2 tw[192];
    int b = blockIdx.y, t = threadIdx.x, ty = threadIdx.y;
    int y = blockIdx.x * 8 + ty + 1;
    bool ok = (y <= 127);
    build_tw(tw, ty * 64 + t, 1.0f);
    const float* rrow = g_r + (b * NN + (ok ? (y - 1) : 0) * 127);
#pragma unroll
    for (int k = 0; k < 4; ++k) {
        int p = t + k * 64;
        float v = 0.0f;
        if (ok) {
            if (p >= 1 && p <= 127)  v =  rrow[p - 1];
            else if (p >= 129)       v = -rrow[255 - p];
        }
        s[ty][dr4(p)] = make_float2(v, 0.0f);
    }
    __syncthreads();
    fft256_r4<1, 1>(s[ty], tw, t);
    if (ok) {
        float2* base = g_FA + (size_t)b * IMG;
#pragma unroll
        for (int k = 0; k < 2; ++k) {
            int kk = t + k * 64;
            float2 v0 = s[ty][kk];
            base[y * 256 + kk]         = v0;
            base[(256 - y) * 256 + kk] = make_float2(-v0.x, -v0.y);
            if (y == 1) {
                base[kk]             = make_float2(0.f, 0.f);
                base[128 * 256 + kk] = make_float2(0.f, 0.f);
            }
        }
    }
}

// ifft2 pass 2: 8 cols/block (grid 16 x NB), output purely REAL.
__global__ void __launch_bounds__(512)
fft_col_inv(const int* __restrict__ ep, int iter) {
    if (iter >= get_K(ep)) return;
    __shared__ float2 s[256 * 8];
    __shared__ float2 tw[192];
    int b  = blockIdx.y;
    int tx = threadIdx.x, ty = threadIdx.y;     // 8 x 64
    int tid = ty * 8 + tx;
    int x = blockIdx.x * 8 + tx;                // 0..127
    build_tw(tw, tid, 1.0f);
#pragma unroll
    for (int k = 0; k < 4; ++k) {
        int r = ty + k * 64;
        s[dr4(r) * 8 + tx] = g_FA[(b * 256 + r) * 256 + x];
    }
    __syncthreads();
    fft256_r4<8, 1>(s + tx, tw, ty);
    const float sc = 1.0f / 65536.0f;
    float* FB = (float*)g_FB;
#pragma unroll
    for (int k = 0; k < 4; ++k) {
        int r = ty + k * 64;
        float val = s[r * 8 + tx].x * sc;
        int n2 = (r ^ 128);
        float* row = FB + (size_t)b * IMG + n2 * 256;
        if (x == 0) {
            row[128] = val;
            row[0]   = 0.0f;
        } else {
            row[x + 128] = val;
            row[128 - x] = -val;
        }
    }
}

// Fused 3-conv stack with packed f32x2 complex MACs.
template <bool ADJ>
__global__ void __launch_bounds__(512, 2)
fused_stack(const float* __restrict__ inR, const float2* __restrict__ inC,
            float2* __restrict__ out,
            const float* __restrict__ w1r, const float* __restrict__ w1i,
            const float* __restrict__ w2r, const float* __restrict__ w2i,
            const float* __restrict__ w3r, const float* __restrict__ w3i,
            const float* __restrict__ thr, const float* __restrict__ thi,
            const int* __restrict__ ep, int iter) {
    if (iter >= get_K(ep)) return;
    extern __shared__ char smc[];
    float*      INr  = (float*)smc;
    float2*     INc  = (float2*)smc;
    float2*     T1   = (float2*)(smc + 11552);
    ulonglong2* Wb   = (ulonglong2*)(smc + 11552 + 41472);
    u64*        Wa01 = (u64*)(smc + 11552 + 41472 + 2304);
    u64*        Wa23 = Wa01 + 36;
    ulonglong2* Wc2  = (ulonglong2*)(Wa23 + 36);

    int b   = blockIdx.z;
    int ox  = blockIdx.x * 32;
    int oy  = blockIdx.y * 32;
    int tid = threadIdx.x;

    if (tid < 216) {
        if (tid < 144) {
            int u = tid;
            int co = u & 3, tap = (u >> 2) % 9, ci = u / 36;
            float wr, wi;
            if (!ADJ) {
                int j = ((b * 4 + co) * 4 + ci) * 9 + tap;
                wr = w2r[j]; wi = w2i[j];
            } else {
                int tt = (tap % 3) * 3 + tap / 3;
                int j = ((b * 4 + ci) * 4 + co) * 9 + tt;
                wr = w2r[j]; wi = -w2i[j];
            }
            ulonglong2 wv; wv.x = pk2(wr, wi); wv.y = pk2(-wi, wr);
            Wb[(ci * 9 + tap) * 4 + co] = wv;
        } else if (tid < 180) {
            int u = tid - 144;
            int tap = u >> 2, co = u & 3;
            float wr, wi;
            if (!ADJ) {
                int j = (b * 4 + co) * 9 + tap;
                wr = w1r[j]; wi = w1i[j];
            } else {
                int tt = (tap % 3) * 3 + tap / 3;
                int j = (b * 4 + co) * 9 + tt;
                wr = w3r[j]; wi = -w3i[j];
            }
            Wa01[u] = pk2(wr, wi);
            Wa23[u] = pk2(-wi, wr);
        } else {
            int u = tid - 180;
            int ci = u / 9, tap = u % 9;
            float wr, wi;
            if (!ADJ) {
                int j = (b * 4 + ci) * 9 + tap;
                wr = w3r[j]; wi = w3i[j];
            } else {
                int tt = (tap % 3) * 3 + tap / 3;
                int j = (b * 4 + ci) * 9 + tt;
                wr = w1r[j]; wi = -w1i[j];
            }
            ulonglong2 wv; wv.x = pk2(wr, wi); wv.y = pk2(-wi, wr);
            Wc2[u] = wv;
        }
    }

    for (int i = tid; i < 38 * 38; i += 512) {
        int iy = i / 38, ix = i % 38;
        int gy = oy - 3 + iy, gx = ox - 3 + ix;
        bool in = ((unsigned)gy < 256u) && ((unsigned)gx < 256u);
        if (!ADJ) {
            INr[i] = in ? inR[(size_t)b * IMG + gy * 256 + gx] : 0.0f;
        } else {
            INc[i] = in ? inC[(size_t)b * IMG + gy * 256 + gx] : make_float2(0.f, 0.f);
        }
    }
    __syncthreads();

    // stage 1: 1 -> 4 over 36x36
    for (int p = tid; p < 1296; p += 512) {
        int py = p / 36, px = p % 36;
        int gy = oy - 2 + py, gx = ox - 2 + px;
        u64 a0 = 0, a1 = 0, a2 = 0, a3 = 0;
        if ((unsigned)gy < 256u && (unsigned)gx < 256u) {
            int base = py * 38 + px;
#pragma unroll
            for (int tap = 0; tap < 9; ++tap) {
                int off = base + (tap / 3) * 38 + tap % 3;
                if (!ADJ) {
                    float sv = INr[off];
                    u64 va = pk2(sv, sv);
                    cfma(a0, va, Wa01[tap * 4 + 0]);
                    cfma(a1, va, Wa01[tap * 4 + 1]);
                    cfma(a2, va, Wa01[tap * 4 + 2]);
                    cfma(a3, va, Wa01[tap * 4 + 3]);
                } else {
                    float2 v = INc[off];
                    u64 va = pk2(v.x, v.x), vb = pk2(v.y, v.y);
                    cfma(a0, va, Wa01[tap * 4 + 0]); cfma(a0, vb, Wa23[tap * 4 + 0]);
                    cfma(a1, va, Wa01[tap * 4 + 1]); cfma(a1, vb, Wa23[tap * 4 + 1]);
                    cfma(a2, va, Wa01[tap * 4 + 2]); cfma(a2, vb, Wa23[tap * 4 + 2]);
                    cfma(a3, va, Wa01[tap * 4 + 3]); cfma(a3, vb, Wa23[tap * 4 + 3]);
                }
            }
        }
        T1[0 * 1296 + p] = upk(a0);
        T1[1 * 1296 + p] = upk(a1);
        T1[2 * 1296 + p] = upk(a2);
        T1[3 * 1296 + p] = upk(a3);
    }
    __syncthreads();

    // stage 2: 4 -> 4 over 34x34
    {
        u64 acc[3][4];
        int bidx[3];
        bool val[3];
#pragma unroll
        for (int k = 0; k < 3; ++k) {
            int p = tid + k * 512;
            val[k] = p < 1156;
            int pc = val[k] ? p : 1155;
            int py = pc / 34, px = pc - py * 34;
            bidx[k] = py * 36 + px;
#pragma unroll
            for (int c = 0; c < 4; ++c) acc[k][c] = 0;
        }
#pragma unroll
        for (int ci = 0; ci < 4; ++ci) {
            const float2* Tci = T1 + ci * 1296;
#pragma unroll
            for (int tap = 0; tap < 9; ++tap) {
                ulonglong2 w0 = Wb[(ci * 9 + tap) * 4 + 0];
                ulonglong2 w1 = Wb[(ci * 9 + tap) * 4 + 1];
                ulonglong2 w2 = Wb[(ci * 9 + tap) * 4 + 2];
                ulonglong2 w3 = Wb[(ci * 9 + tap) * 4 + 3];
                int off = (tap / 3) * 36 + tap % 3;
#pragma unroll
                for (int k = 0; k < 3; ++k) {
                    float2 v = Tci[bidx[k] + off];
                    u64 va = pk2(v.x, v.x), vb = pk2(v.y, v.y);
                    cfma(acc[k][0], va, w0.x); cfma(acc[k][0], vb, w0.y);
                    cfma(acc[k][1], va, w1.x); cfma(acc[k][1], vb, w1.y);
                    cfma(acc[k][2], va, w2.x); cfma(acc[k][2], vb, w2.y);
                    cfma(acc[k][3], va, w3.x); cfma(acc[k][3], vb, w3.y);
                }
            }
        }
        __syncthreads();
#pragma unroll
        for (int k = 0; k < 3; ++k) {
            if (val[k]) {
                int p = tid + k * 512;
                int py = p / 34, px = p - py * 34;
                int gy = oy - 1 + py, gx = ox - 1 + px;
                bool in2 = ((unsigned)gy < 256u) && ((unsigned)gx < 256u);
#pragma unroll
                for (int c = 0; c < 4; ++c)
                    T1[c * 1156 + p] = in2 ? upk(acc[k][c]) : make_float2(0.f, 0.f);
            }
        }
    }
    __syncthreads();

    // stage 3: 4 -> 1 over 32x32
    {
        u64 acc[2];
        int bidx[2];
#pragma unroll
        for (int k = 0; k < 2; ++k) {
            int p = tid + k * 512;
            int py = p >> 5, px = p & 31;
            bidx[k] = py * 34 + px;
            acc[k] = 0;
        }
#pragma unroll
        for (int ci = 0; ci < 4; ++ci) {
            const float2* Tci = T1 + ci * 1156;
#pragma unroll
            for (int tap = 0; tap < 9; ++tap) {
                ulonglong2 w = Wc2[ci * 9 + tap];
                int off = (tap / 3) * 34 + tap % 3;
#pragma unroll
                for (int k = 0; k < 2; ++k) {
                    float2 v = Tci[bidx[k] + off];
                    cfma(acc[k], pk2(v.x, v.x), w.x);
                    cfma(acc[k], pk2(v.y, v.y), w.y);
                }
            }
        }
        float2* ob = out + (size_t)b * IMG;
#pragma unroll
        for (int k = 0; k < 2; ++k) {
            int p = tid + k * 512;
            int py = p >> 5, px = p & 31;
            int gidx = (oy + py) * 256 + (ox + px);
            float2 a = upk(acc[k]);
            if (!ADJ) {
                float tr = thr[b * IMG + gidx], ti = thi[b * IMG + gidx];
                u64 r = 0;
                cfma(r, pk2(a.x, a.x), pk2(tr, ti));
                cfma(r, pk2(a.y, a.y), pk2(-ti, tr));
                a = upk(r);
            }
            ob[gidx] = a;
        }
    }
}

// fft2 pass 1: ifftshift on read, forward FFT along x; store k=0..127 only.
__global__ void __launch_bounds__(512)
fft_row_fwd(const int* __restrict__ ep, int iter) {
    if (iter >= get_K(ep)) return;
    __shared__ float2 s[8][256];
    __shared__ float2 tw[192];
    int b = blockIdx.y, t = threadIdx.x, ty = threadIdx.y;
    int y = blockIdx.x * 8 + ty;
    build_tw(tw, ty * 64 + t, -1.0f);
    const float2* irow = g_FB + (b * 256 + (y ^ 128)) * 256;
#pragma unroll
    for (int k = 0; k < 4; ++k) {
        int p = t + k * 64;
        s[ty][dr4(p)] = irow[p ^ 128];
    }
    __syncthreads();
    fft256_r4<1, -1>(s[ty], tw, t);
    float2* orow = g_FA + (b * 256 + y) * 256;
    orow[t]      = s[ty][t];
    orow[t + 64] = s[ty][t + 64];
}

// fft2 pass 2: 8 cols/block (grid 16 x NB), crop 127x127, accumulate into x.
__global__ void __launch_bounds__(512)
fft_col_fwd_accum(const int* __restrict__ ep, int iter) {
    if (iter >= get_K(ep)) return;
    __shared__ float2 s[256 * 8];
    __shared__ float2 tw[192];
    int b  = blockIdx.y;
    int tx = threadIdx.x, ty = threadIdx.y;     // 8 x 64
    int tid = ty * 8 + tx;
    int x = blockIdx.x * 8 + tx;                // 0..127
    build_tw(tw, tid, -1.0f);
#pragma unroll
    for (int k = 0; k < 4; ++k) {
        int r = ty + k * 64;
        s[dr4(r) * 8 + tx] = g_FA[(b * 256 + r) * 256 + x];
    }
    __syncthreads();
    fft256_r4<8, -1>(s + tx, tw, ty);
    if (x < 127) {
#pragma unroll
        for (int k = 0; k < 4; ++k) {
            int r = ty + k * 64;
            if (r < 127)
                g_x[b * NN + r * 127 + x] += s[r * 8 + tx].x;
        }
    }
}

// Residual norm.
__global__ void __launch_bounds__(256)
norm_partial(const float* __restrict__ f, const float* __restrict__ kA) {
    __shared__ float sr_s[256], sf_s[256];
    int b = blockIdx.y;
    int row = blockIdx.x * 2 + (threadIdx.x >> 7);
    int col = threadIdx.x & 127;
    float sr = 0.0f, sf = 0.0f;
    if (row < 127 && col < 127) {
        int p = row * 127 + col;
        const float* ka = kA + b * 9;
        const float* xb = g_x + b * NN;
        float s = 0.0f;
        if (row > 0) {
            if (col > 0)   s += ka[0] * xb[p - 128];
            s += ka[1] * xb[p - 127];
            if (col < 126) s += ka[2] * xb[p - 126];
        }
        if (col > 0)   s += ka[3] * xb[p - 1];
        s += ka[4] * xb[p];
        if (col < 126) s += ka[5] * xb[p + 1];
        if (row < 126) {
            if (col > 0)   s += ka[6] * xb[p + 126];
            s += ka[7] * xb[p + 127];
            if (col < 126) s += ka[8] * xb[p + 128];
        }
        float fv = f[b * NN + p];
        float rv = fv - s;
        sr = rv * rv;
        sf = fv * fv;
    }
    sr_s[threadIdx.x] = sr;
    sf_s[threadIdx.x] = sf;
    __syncthreads();
    for (int o = 128; o > 0; o >>= 1) {
        if (threadIdx.x < o) {
            sr_s[threadIdx.x] += sr_s[threadIdx.x + o];
            sf_s[threadIdx.x] += sf_s[threadIdx.x + o];
        }
        __syncthreads();
    }
    if (threadIdx.x == 0) g_part[b * 64 + blockIdx.x] = make_float2(sr_s[0], sf_s[0]);
}

__global__ void norm_final(float* __restrict__ out) {
    __shared__ float sr_s[256], sf_s[256];
    float sr = 0.0f, sf = 0.0f;
#pragma unroll
    for (int k = 0; k < 4; ++k) {
        float2 v = g_part[threadIdx.x + k * 256];
        sr += v.x; sf += v.y;
    }
    sr_s[threadIdx.x] = sr;
    sf_s[threadIdx.x] = sf;
    __syncthreads();
    for (int o = 128; o > 0; o >>= 1) {
        if (threadIdx.x < o) {
            sr_s[threadIdx.x] += sr_s[threadIdx.x + o];
            sf_s[threadIdx.x] += sf_s[threadIdx.x + o];
        }
        __syncthreads();
    }
    if (threadIdx.x == 0) out[0] = sqrtf(sr_s[0] / sf_s[0]);
}

// ---------------- launch ------------------------------------------------------
extern "C" void kernel_launch(void* const* d_in, const int* in_sizes, int n_in,
                              void* d_out, int out_size) {
    (void)in_sizes; (void)n_in; (void)out_size;
    const float* f   = (const float*)d_in[0];
    const float* kA  = (const float*)d_in[1];
    const float* w1r = (const float*)d_in[2];
    const float* w1i = (const float*)d_in[3];
    const float* w2r = (const float*)d_in[4];
    const float* w2i = (const float*)d_in[5];
    const float* w3r = (const float*)d_in[6];
    const float* w3i = (const float*)d_in[7];
    const float* thr = (const float*)d_in[8];
    const float* thi = (const float*)d_in[9];
    const int*   ep  = (const int*)d_in[10];
    float* out = (float*)d_out;

    void *pFA = nullptr, *pFB = nullptr;
    cudaGetSymbolAddress(&pFA, g_FA);
    cudaGetSymbolAddress(&pFB, g_FB);

    const int FSM = 11552 + 41472 + 2304 + 288 + 288 + 576;   // 56480 B
    cudaFuncSetAttribute(fused_stack<false>, cudaFuncAttributeMaxDynamicSharedMemorySize, FSM);
    cudaFuncSetAttribute(fused_stack<true>,  cudaFuncAttributeMaxDynamicSharedMemorySize, FSM);

    dim3 jg(4, 4, NB);
    for (int it = 0; it < 3; ++it) {
        jacobi_tile<<<jg, 512>>>(f, kA, ep, it, 0, it == 0 ? 1 : 0);
        jacobi_tile<<<jg, 512>>>(f, kA, ep, it, 1, 0);
        fft_row_expand<<<dim3(16, NB), dim3(64, 8)>>>(ep, it);
        fft_col_inv<<<dim3(16, NB), dim3(8, 64)>>>(ep, it);
        fused_stack<false><<<dim3(8, 8, NB), 512, FSM>>>(
            (const float*)pFB, nullptr, (float2*)pFA,
            w1r, w1i, w2r, w2i, w3r, w3i, thr, thi, ep, it);
        fused_stack<true><<<dim3(8, 8, NB), 512, FSM>>>(
            nullptr, (const float2*)pFA, (float2*)pFB,
            w1r, w1i, w2r, w2i, w3r, w3i, nullptr, nullptr, ep, it);
        fft_row_fwd<<<dim3(32, NB), dim3(64, 8)>>>(ep, it);
        fft_col_fwd_accum<<<dim3(16, NB), dim3(8, 64)>>>(ep, it);
    }

    norm_partial<<<dim3(64, NB), 256>>>(f, kA);
    norm_final<<<1, 256>>>(out);
}

// round 10
// speedup vs baseline: 1.0152x; 1.0152x over previous
#include <cuda_runtime.h>
#include <math.h>

#define NB   16
#define NI   127
#define NN   16129      // 127*127
#define IMG  65536      // 256*256
#define TS   32
#define HL2  11
#define LT2  54         // TS + 2*HL2
#define LTN  2916       // LT2*LT2
#define CST  17         // column-FFT smem stride (odd => conflict-free)

typedef unsigned long long u64;

// ---------------- scratch (static device globals) ----------------------------
static __device__ float  g_x[NB * NN];
static __device__ float  g_r[NB * NN];
static __device__ float2 g_FA[NB * IMG];
static __device__ float2 g_FB[NB * IMG];   // also reused as float (real) buffer
static __device__ float2 g_part[1024];

// ---------------- packed f32x2 helpers ---------------------------------------
__device__ __forceinline__ u64 pk2(float lo, float hi) {
    u64 r; asm("mov.b64 %0, {%1, %2};" : "=l"(r) : "f"(lo), "f"(hi)); return r;
}
__device__ __forceinline__ float2 upk(u64 v) {
    float2 r; asm("mov.b64 {%0, %1}, %2;" : "=f"(r.x), "=f"(r.y) : "l"(v)); return r;
}
__device__ __forceinline__ void cfma(u64& acc, u64 a, u64 b) {
    asm("fma.rn.f32x2 %0, %1, %2, %0;" : "+l"(acc) : "l"(a), "l"(b));
}

// ---------------- misc helpers ------------------------------------------------
__device__ __forceinline__ int get_K(const int* ep) {
    int ei = *ep;
    int e;
    if (ei > 0 && ei <= 1000000) {
        e = ei;
    } else {
        float ff = __int_as_float(ei);
        e = (ff >= 1.0f && ff <= 1000000.0f) ? (int)ff : 120;
    }
    int K = (e - 1) / 40 + 1;
    if (K > 10) K = 10;
    if (K < 1)  K = 1;
    return K;
}

// base-4 digit reversal of 8-bit index
__device__ __forceinline__ int dr4(int p) {
    return ((p & 3) << 6) | (((p >> 2) & 3) << 4) | (((p >> 4) & 3) << 2) | ((p >> 6) & 3);
}

__device__ __forceinline__ float2 cmulf(float2 a, float2 b) {
    return make_float2(a.x * b.x - a.y * b.y, a.x * b.y + a.y * b.x);
}

__device__ __forceinline__ void build_tw(float2* tw, int tid, float sign) {
    if (tid < 192) {
        float s, c;
        __sincosf(sign * 6.283185307179586f * (float)tid * (1.0f / 256.0f), &s, &c);
        tw[tid] = make_float2(c, s);
    }
}

// Radix-4 256-pt DIT FFT, input base-4 digit-reversed, output natural.
// 64 butterflies/stage, t in 0..63; 4 stages. SGN=+1 inverse / -1 forward.
template <int STRIDE, int SGN>
__device__ __forceinline__ void fft256_r4(float2* s, const float2* tw, int t) {
#pragma unroll
    for (int st = 0; st < 4; ++st) {
        int L    = 1 << (2 * st);
        int k    = t & (L - 1);
        int g    = t >> (2 * st);
        int i0   = g * 4 * L + k;
        int step = 64 >> (2 * st);
        float2 a = s[i0 * STRIDE];
        float2 b = s[(i0 + L) * STRIDE];
        float2 c = s[(i0 + 2 * L) * STRIDE];
        float2 d = s[(i0 + 3 * L) * STRIDE];
        b = cmulf(b, tw[k * step]);
        c = cmulf(c, tw[2 * k * step]);
        d = cmulf(d, tw[3 * k * step]);
        float2 t0 = make_float2(a.x + c.x, a.y + c.y);
        float2 t1 = make_float2(a.x - c.x, a.y - c.y);
        float2 t2 = make_float2(b.x + d.x, b.y + d.y);
        float2 t3 = make_float2(b.x - d.x, b.y - d.y);
        float2 rot = make_float2(-(float)SGN * t3.y, (float)SGN * t3.x);
        s[i0 * STRIDE]           = make_float2(t0.x + t2.x, t0.y + t2.y);
        s[(i0 + L) * STRIDE]     = make_float2(t1.x + rot.x, t1.y + rot.y);
        s[(i0 + 2 * L) * STRIDE] = make_float2(t0.x - t2.x, t0.y - t2.y);
        s[(i0 + 3 * L) * STRIDE] = make_float2(t1.x - rot.x, t1.y - rot.y);
        __syncthreads();
    }
}

// ---------------- kernels ----------------------------------------------------
// Sweep-chunked Jacobi: 10 sweeps/launch on 54x54 tiles (halo 11), 512 threads.
__global__ void __launch_bounds__(512)
jacobi_tile(const float* __restrict__ f, const float* __restrict__ kA,
            const int* __restrict__ ep, int iter, int final_, int zero) {
    if (iter >= get_K(ep)) return;
    __shared__ float xs0[LTN], xs1[LTN], fs[LTN];
    int b  = blockIdx.z;
    int ox = blockIdx.x * TS - HL2;
    int oy = blockIdx.y * TS - HL2;
    int tid = threadIdx.x;
    const float* ka = kA + b * 9;
    float k0 = ka[0], k1 = ka[1], k2 = ka[2], k3 = ka[3], k4 = ka[4];
    float k5 = ka[5], k6 = ka[6], k7 = ka[7], k8 = ka[8];
    float tau = 0.5f / k4;

    int  iyk[6], ixk[6];
    bool okk[6], domk[6];
#pragma unroll
    for (int k = 0; k < 6; ++k) {
        int p = tid + k * 512;
        bool ok = p < LTN;
        int iy = 0, ix = 0;
        if (ok) { iy = p / LT2; ix = p - iy * LT2; }
        int gy = oy + iy, gx = ox + ix;
        bool dom = ok && ((unsigned)gy < 127u) && ((unsigned)gx < 127u);
        if (ok) {
            xs0[p] = (dom && !zero) ? g_x[b * NN + gy * 127 + gx] : 0.0f;
            fs[p]  = dom ? f[b * NN + gy * 127 + gx] : 0.0f;
        }
        iyk[k] = iy; ixk[k] = ix; okk[k] = ok; domk[k] = dom;
    }
    __syncthreads();

    float* cur = xs0;
    float* nxt = xs1;
#pragma unroll
    for (int s = 0; s < 10; ++s) {
        int a = s + 1;
#pragma unroll
        for (int k = 0; k < 6; ++k) {
            if (okk[k]) {
                int p = tid + k * 512;
                float nv = cur[p];
                int iy = iyk[k], ix = ixk[k];
                if (domk[k] && iy >= a && iy < LT2 - a && ix >= a && ix < LT2 - a) {
                    float ax = k0 * cur[p - LT2 - 1] + k1 * cur[p - LT2] + k2 * cur[p - LT2 + 1]
                             + k3 * cur[p - 1]       + k4 * cur[p]       + k5 * cur[p + 1]
                             + k6 * cur[p + LT2 - 1] + k7 * cur[p + LT2] + k8 * cur[p + LT2 + 1];
                    nv = cur[p] + tau * (fs[p] - ax);
                }
                nxt[p] = nv;
            }
        }
        __syncthreads();
        float* tsw = cur; cur = nxt; nxt = tsw;
    }

#pragma unroll
    for (int k = 0; k < 2; ++k) {
        int p2 = tid + k * 512;
        int py = p2 >> 5, px = p2 & 31;
        int iy = HL2 + py, ix = HL2 + px;
        int gy = oy + iy, gx = ox + ix;
        if (((unsigned)gy < 127u) && ((unsigned)gx < 127u)) {
            int i = iy * LT2 + ix;
            g_x[b * NN + gy * 127 + gx] = cur[i];
            if (final_) {
                float ax = k0 * cur[i - LT2 - 1] + k1 * cur[i - LT2] + k2 * cur[i - LT2 + 1]
                         + k3 * cur[i - 1]       + k4 * cur[i]       + k5 * cur[i + 1]
                         + k6 * cur[i + LT2 - 1] + k7 * cur[i + LT2] + k8 * cur[i + LT2 + 1];
                g_r[b * NN + gy * 127 + gx] = fs[i] - ax;
            }
        }
    }
}

// ifft2 pass 1 (odd symmetry): FFT rows 1..127; store only k=0..127.
__global__ void __launch_bounds__(512)
fft_row_expand(const int* __restrict__ ep, int iter) {
    if (iter >= get_K(ep)) return;
    __shared__ float2 s[8][256];
    __shared__ float2 tw[192];
    int b = blockIdx.y, t = threadIdx.x, ty = threadIdx.y;
    int y = blockIdx.x * 8 + ty + 1;
    bool ok = (y <= 127);
    build_tw(tw, ty * 64 + t, 1.0f);
    const float* rrow = g_r + (b * NN + (ok ? (y - 1) : 0) * 127);
#pragma unroll
    for (int k = 0; k < 4; ++k) {
        int p = t + k * 64;
        float v = 0.0f;
        if (ok) {
            if (p >= 1 && p <= 127)  v =  rrow[p - 1];
            else if (p >= 129)       v = -rrow[255 - p];
        }
        s[ty][dr4(p)] = make_float2(v, 0.0f);
    }
    __syncthreads();
    fft256_r4<1, 1>(s[ty], tw, t);
    if (ok) {
        float2* base = g_FA + (size_t)b * IMG;
#pragma unroll
        for (int k = 0; k < 2; ++k) {
            int kk = t + k * 64;
            float2 v0 = s[ty][kk];
            base[y * 256 + kk]         = v0;
            base[(256 - y) * 256 + kk] = make_float2(-v0.x, -v0.y);
            if (y == 1) {
                base[kk]             = make_float2(0.f, 0.f);
                base[128 * 256 + kk] = make_float2(0.f, 0.f);
            }
        }
    }
}

// ifft2 pass 2: columns 0..127, 16 cols/block, stride-17 padded smem
// (bank-conflict-free), output purely REAL.
__global__ void __launch_bounds__(1024)
fft_col_inv(const int* __restrict__ ep, int iter) {
    if (iter >= get_K(ep)) return;
    __shared__ float2 s[256 * CST];
    __shared__ float2 tw[192];
    int b  = blockIdx.y;
    int tx = threadIdx.x, ty = threadIdx.y;     // 16 x 64
    int tid = ty * 16 + tx;
    int x = blockIdx.x * 16 + tx;               // 0..127
    build_tw(tw, tid, 1.0f);
#pragma unroll
    for (int k = 0; k < 4; ++k) {
        int r = ty + k * 64;
        s[dr4(r) * CST + tx] = g_FA[(b * 256 + r) * 256 + x];
    }
    __syncthreads();
    fft256_r4<CST, 1>(s + tx, tw, ty);
    const float sc = 1.0f / 65536.0f;
    float* FB = (float*)g_FB;
#pragma unroll
    for (int k = 0; k < 4; ++k) {
        int r = ty + k * 64;
        float val = s[r * CST + tx].x * sc;
        int n2 = (r ^ 128);
        float* row = FB + (size_t)b * IMG + n2 * 256;
        if (x == 0) {
            row[128] = val;
            row[0]   = 0.0f;
        } else {
            row[x + 128] = val;
            row[128 - x] = -val;
        }
    }
}

// Fused 3-conv stack with packed f32x2 complex MACs.
template <bool ADJ>
__global__ void __launch_bounds__(512, 2)
fused_stack(const float* __restrict__ inR, const float2* __restrict__ inC,
            float2* __restrict__ out,
            const float* __restrict__ w1r, const float* __restrict__ w1i,
            const float* __restrict__ w2r, const float* __restrict__ w2i,
            const float* __restrict__ w3r, const float* __restrict__ w3i,
            const float* __restrict__ thr, const float* __restrict__ thi,
            const int* __restrict__ ep, int iter) {
    if (iter >= get_K(ep)) return;
    extern __shared__ char smc[];
    float*      INr  = (float*)smc;
    float2*     INc  = (float2*)smc;
    float2*     T1   = (float2*)(smc + 11552);
    ulonglong2* Wb   = (ulonglong2*)(smc + 11552 + 41472);
    u64*        Wa01 = (u64*)(smc + 11552 + 41472 + 2304);
    u64*        Wa23 = Wa01 + 36;
    ulonglong2* Wc2  = (ulonglong2*)(Wa23 + 36);

    int b   = blockIdx.z;
    int ox  = blockIdx.x * 32;
    int oy  = blockIdx.y * 32;
    int tid = threadIdx.x;

    if (tid < 216) {
        if (tid < 144) {
            int u = tid;
            int co = u & 3, tap = (u >> 2) % 9, ci = u / 36;
            float wr, wi;
            if (!ADJ) {
                int j = ((b * 4 + co) * 4 + ci) * 9 + tap;
                wr = w2r[j]; wi = w2i[j];
            } else {
                int tt = (tap % 3) * 3 + tap / 3;
                int j = ((b * 4 + ci) * 4 + co) * 9 + tt;
                wr = w2r[j]; wi = -w2i[j];
            }
            ulonglong2 wv; wv.x = pk2(wr, wi); wv.y = pk2(-wi, wr);
            Wb[(ci * 9 + tap) * 4 + co] = wv;
        } else if (tid < 180) {
            int u = tid - 144;
            int tap = u >> 2, co = u & 3;
            float wr, wi;
            if (!ADJ) {
                int j = (b * 4 + co) * 9 + tap;
                wr = w1r[j]; wi = w1i[j];
            } else {
                int tt = (tap % 3) * 3 + tap / 3;
                int j = (b * 4 + co) * 9 + tt;
                wr = w3r[j]; wi = -w3i[j];
            }
            Wa01[u] = pk2(wr, wi);
            Wa23[u] = pk2(-wi, wr);
        } else {
            int u = tid - 180;
            int ci = u / 9, tap = u % 9;
            float wr, wi;
            if (!ADJ) {
                int j = (b * 4 + ci) * 9 + tap;
                wr = w3r[j]; wi = w3i[j];
            } else {
                int tt = (tap % 3) * 3 + tap / 3;
                int j = (b * 4 + ci) * 9 + tt;
                wr = w1r[j]; wi = -w1i[j];
            }
            ulonglong2 wv; wv.x = pk2(wr, wi); wv.y = pk2(-wi, wr);
            Wc2[u] = wv;
        }
    }

    for (int i = tid; i < 38 * 38; i += 512) {
        int iy = i / 38, ix = i % 38;
        int gy = oy - 3 + iy, gx = ox - 3 + ix;
        bool in = ((unsigned)gy < 256u) && ((unsigned)gx < 256u);
        if (!ADJ) {
            INr[i] = in ? inR[(size_t)b * IMG + gy * 256 + gx] : 0.0f;
        } else {
            INc[i] = in ? inC[(size_t)b * IMG + gy * 256 + gx] : make_float2(0.f, 0.f);
        }
    }
    __syncthreads();

    // stage 1: 1 -> 4 over 36x36
    for (int p = tid; p < 1296; p += 512) {
        int py = p / 36, px = p % 36;
        int gy = oy - 2 + py, gx = ox - 2 + px;
        u64 a0 = 0, a1 = 0, a2 = 0, a3 = 0;
        if ((unsigned)gy < 256u && (unsigned)gx < 256u) {
            int base = py * 38 + px;
#pragma unroll
            for (int tap = 0; tap < 9; ++tap) {
                int off = base + (tap / 3) * 38 + tap % 3;
                if (!ADJ) {
                    float sv = INr[off];
                    u64 va = pk2(sv, sv);
                    cfma(a0, va, Wa01[tap * 4 + 0]);
                    cfma(a1, va, Wa01[tap * 4 + 1]);
                    cfma(a2, va, Wa01[tap * 4 + 2]);
                    cfma(a3, va, Wa01[tap * 4 + 3]);
                } else {
                    float2 v = INc[off];
                    u64 va = pk2(v.x, v.x), vb = pk2(v.y, v.y);
                    cfma(a0, va, Wa01[tap * 4 + 0]); cfma(a0, vb, Wa23[tap * 4 + 0]);
                    cfma(a1, va, Wa01[tap * 4 + 1]); cfma(a1, vb, Wa23[tap * 4 + 1]);
                    cfma(a2, va, Wa01[tap * 4 + 2]); cfma(a2, vb, Wa23[tap * 4 + 2]);
                    cfma(a3, va, Wa01[tap * 4 + 3]); cfma(a3, vb, Wa23[tap * 4 + 3]);
                }
            }
        }
        T1[0 * 1296 + p] = upk(a0);
        T1[1 * 1296 + p] = upk(a1);
        T1[2 * 1296 + p] = upk(a2);
        T1[3 * 1296 + p] = upk(a3);
    }
    __syncthreads();

    // stage 2: 4 -> 4 over 34x34
    {
        u64 acc[3][4];
        int bidx[3];
        bool val[3];
#pragma unroll
        for (int k = 0; k < 3; ++k) {
            int p = tid + k * 512;
            val[k] = p < 1156;
            int pc = val[k] ? p : 1155;
            int py = pc / 34, px = pc - py * 34;
            bidx[k] = py * 36 + px;
#pragma unroll
            for (int c = 0; c < 4; ++c) acc[k][c] = 0;
        }
#pragma unroll
        for (int ci = 0; ci < 4; ++ci) {
            const float2* Tci = T1 + ci * 1296;
#pragma unroll
            for (int tap = 0; tap < 9; ++tap) {
                ulonglong2 w0 = Wb[(ci * 9 + tap) * 4 + 0];
                ulonglong2 w1 = Wb[(ci * 9 + tap) * 4 + 1];
                ulonglong2 w2 = Wb[(ci * 9 + tap) * 4 + 2];
                ulonglong2 w3 = Wb[(ci * 9 + tap) * 4 + 3];
                int off = (tap / 3) * 36 + tap % 3;
#pragma unroll
                for (int k = 0; k < 3; ++k) {
                    float2 v = Tci[bidx[k] + off];
                    u64 va = pk2(v.x, v.x), vb = pk2(v.y, v.y);
                    cfma(acc[k][0], va, w0.x); cfma(acc[k][0], vb, w0.y);
                    cfma(acc[k][1], va, w1.x); cfma(acc[k][1], vb, w1.y);
                    cfma(acc[k][2], va, w2.x); cfma(acc[k][2], vb, w2.y);
                    cfma(acc[k][3], va, w3.x); cfma(acc[k][3], vb, w3.y);
                }
            }
        }
        __syncthreads();
#pragma unroll
        for (int k = 0; k < 3; ++k) {
            if (val[k]) {
                int p = tid + k * 512;
                int py = p / 34, px = p - py * 34;
                int gy = oy - 1 + py, gx = ox - 1 + px;
                bool in2 = ((unsigned)gy < 256u) && ((unsigned)gx < 256u);
#pragma unroll
                for (int c = 0; c < 4; ++c)
                    T1[c * 1156 + p] = in2 ? upk(acc[k][c]) : make_float2(0.f, 0.f);
            }
        }
    }
    __syncthreads();

    // stage 3: 4 -> 1 over 32x32
    {
        u64 acc[2];
        int bidx[2];
#pragma unroll
        for (int k = 0; k < 2; ++k) {
            int p = tid + k * 512;
            int py = p >> 5, px = p & 31;
            bidx[k] = py * 34 + px;
            acc[k] = 0;
        }
#pragma unroll
        for (int ci = 0; ci < 4; ++ci) {
            const float2* Tci = T1 + ci * 1156;
#pragma unroll
            for (int tap = 0; tap < 9; ++tap) {
                ulonglong2 w = Wc2[ci * 9 + tap];
                int off = (tap / 3) * 34 + tap % 3;
#pragma unroll
                for (int k = 0; k < 2; ++k) {
                    float2 v = Tci[bidx[k] + off];
                    cfma(acc[k], pk2(v.x, v.x), w.x);
                    cfma(acc[k], pk2(v.y, v.y), w.y);
                }
            }
        }
        float2* ob = out + (size_t)b * IMG;
#pragma unroll
        for (int k = 0; k < 2; ++k) {
            int p = tid + k * 512;
            int py = p >> 5, px = p & 31;
            int gidx = (oy + py) * 256 + (ox + px);
            float2 a = upk(acc[k]);
            if (!ADJ) {
                float tr = thr[b * IMG + gidx], ti = thi[b * IMG + gidx];
                u64 r = 0;
                cfma(r, pk2(a.x, a.x), pk2(tr, ti));
                cfma(r, pk2(a.y, a.y), pk2(-ti, tr));
                a = upk(r);
            }
            ob[gidx] = a;
        }
    }
}

// fft2 pass 1: ifftshift on read, forward FFT along x; store k=0..127 only.
__global__ void __launch_bounds__(512)
fft_row_fwd(const int* __restrict__ ep, int iter) {
    if (iter >= get_K(ep)) return;
    __shared__ float2 s[8][256];
    __shared__ float2 tw[192];
    int b = blockIdx.y, t = threadIdx.x, ty = threadIdx.y;
    int y = blockIdx.x * 8 + ty;
    build_tw(tw, ty * 64 + t, -1.0f);
    const float2* irow = g_FB + (b * 256 + (y ^ 128)) * 256;
#pragma unroll
    for (int k = 0; k < 4; ++k) {
        int p = t + k * 64;
        s[ty][dr4(p)] = irow[p ^ 128];
    }
    __syncthreads();
    fft256_r4<1, -1>(s[ty], tw, t);
    float2* orow = g_FA + (b * 256 + y) * 256;
    orow[t]      = s[ty][t];
    orow[t + 64] = s[ty][t + 64];
}

// fft2 pass 2: columns 0..127, 16 cols/block, stride-17 padded smem,
// crop 127x127, accumulate into x.
__global__ void __launch_bounds__(1024)
fft_col_fwd_accum(const int* __restrict__ ep, int iter) {
    if (iter >= get_K(ep)) return;
    __shared__ float2 s[256 * CST];
    __shared__ float2 tw[192];
    int b  = blockIdx.y;
    int tx = threadIdx.x, ty = threadIdx.y;     // 16 x 64
    int tid = ty * 16 + tx;
    int x = blockIdx.x * 16 + tx;
    build_tw(tw, tid, -1.0f);
#pragma unroll
    for (int k = 0; k < 4; ++k) {
        int r = ty + k * 64;
        s[dr4(r) * CST + tx] = g_FA[(b * 256 + r) * 256 + x];
    }
    __syncthreads();
    fft256_r4<CST, -1>(s + tx, tw, ty);
    if (x < 127) {
#pragma unroll
        for (int k = 0; k < 4; ++k) {
            int r = ty + k * 64;
            if (r < 127)
                g_x[b * NN + r * 127 + x] += s[r * CST + tx].x;
        }
    }
}

// Residual norm.
__global__ void __launch_bounds__(256)
norm_partial(const float* __restrict__ f, const float* __restrict__ kA) {
    __shared__ float sr_s[256], sf_s[256];
    int b = blockIdx.y;
    int row = blockIdx.x * 2 + (threadIdx.x >> 7);
    int col = threadIdx.x & 127;
    float sr = 0.0f, sf = 0.0f;
    if (row < 127 && col < 127) {
        int p = row * 127 + col;
        const float* ka = kA + b * 9;
        const float* xb = g_x + b * NN;
        float s = 0.0f;
        if (row > 0) {
            if (col > 0)   s += ka[0] * xb[p - 128];
            s += ka[1] * xb[p - 127];
            if (col < 126) s += ka[2] * xb[p - 126];
        }
        if (col > 0)   s += ka[3] * xb[p - 1];
        s += ka[4] * xb[p];
        if (col < 126) s += ka[5] * xb[p + 1];
        if (row < 126) {
            if (col > 0)   s += ka[6] * xb[p + 126];
            s += ka[7] * xb[p + 127];
            if (col < 126) s += ka[8] * xb[p + 128];
        }
        float fv = f[b * NN + p];
        float rv = fv - s;
        sr = rv * rv;
        sf = fv * fv;
    }
    sr_s[threadIdx.x] = sr;
    sf_s[threadIdx.x] = sf;
    __syncthreads();
    for (int o = 128; o > 0; o >>= 1) {
        if (threadIdx.x < o) {
            sr_s[threadIdx.x] += sr_s[threadIdx.x + o];
            sf_s[threadIdx.x] += sf_s[threadIdx.x + o];
        }
        __syncthreads();
    }
    if (threadIdx.x == 0) g_part[b * 64 + blockIdx.x] = make_float2(sr_s[0], sf_s[0]);
}

__global__ void norm_final(float* __restrict__ out) {
    __shared__ float sr_s[256], sf_s[256];
    float sr = 0.0f, sf = 0.0f;
#pragma unroll
    for (int k = 0; k < 4; ++k) {
        float2 v = g_part[threadIdx.x + k * 256];
        sr += v.x; sf += v.y;
    }
    sr_s[threadIdx.x] = sr;
    sf_s[threadIdx.x] = sf;
    __syncthreads();
    for (int o = 128; o > 0; o >>= 1) {
        if (threadIdx.x < o) {
            sr_s[threadIdx.x] += sr_s[threadIdx.x + o];
            sf_s[threadIdx.x] += sf_s[threadIdx.x + o];
        }
        __syncthreads();
    }
    if (threadIdx.x == 0) out[0] = sqrtf(sr_s[0] / sf_s[0]);
}

// ---------------- launch ------------------------------------------------------
extern "C" void kernel_launch(void* const* d_in, const int* in_sizes, int n_in,
                              void* d_out, int out_size) {
    (void)in_sizes; (void)n_in; (void)out_size;
    const float* f   = (const float*)d_in[0];
    const float* kA  = (const float*)d_in[1];
    const float* w1r = (const float*)d_in[2];
    const float* w1i = (const float*)d_in[3];
    const float* w2r = (const float*)d_in[4];
    const float* w2i = (const float*)d_in[5];
    const float* w3r = (const float*)d_in[6];
    const float* w3i = (const float*)d_in[7];
    const float* thr = (const float*)d_in[8];
    const float* thi = (const float*)d_in[9];
    const int*   ep  = (const int*)d_in[10];
    float* out = (float*)d_out;

    void *pFA = nullptr, *pFB = nullptr;
    cudaGetSymbolAddress(&pFA, g_FA);
    cudaGetSymbolAddress(&pFB, g_FB);

    const int FSM = 11552 + 41472 + 2304 + 288 + 288 + 576;   // 56480 B
    cudaFuncSetAttribute(fused_stack<false>, cudaFuncAttributeMaxDynamicSharedMemorySize, FSM);
    cudaFuncSetAttribute(fused_stack<true>,  cudaFuncAttributeMaxDynamicSharedMemorySize, FSM);

    dim3 jg(4, 4, NB);
    for (int it = 0; it < 3; ++it) {
        jacobi_tile<<<jg, 512>>>(f, kA, ep, it, 0, it == 0 ? 1 : 0);
        jacobi_tile<<<jg, 512>>>(f, kA, ep, it, 1, 0);
        fft_row_expand<<<dim3(16, NB), dim3(64, 8)>>>(ep, it);
        fft_col_inv<<<dim3(8, NB), dim3(16, 64)>>>(ep, it);
        fused_stack<false><<<dim3(8, 8, NB), 512, FSM>>>(
            (const float*)pFB, nullptr, (float2*)pFA,
            w1r, w1i, w2r, w2i, w3r, w3i, thr, thi, ep, it);
        fused_stack<true><<<dim3(8, 8, NB), 512, FSM>>>(
            nullptr, (const float2*)pFA, (float2*)pFB,
            w1r, w1i, w2r, w2i, w3r, w3i, nullptr, nullptr, ep, it);
        fft_row_fwd<<<dim3(32, NB), dim3(64, 8)>>>(ep, it);
        fft_col_fwd_accum<<<dim3(8, NB), dim3(16, 64)>>>(ep, it);
    }

    norm_partial<<<dim3(64, NB), 256>>>(f, kA);
    norm_final<<<1, 256>>>(out);
}